// round 16
// baseline (speedup 1.0000x reference)
#include <cuda_runtime.h>
#include <cstdint>
#include <cstddef>

// Problem dims
#define BB   256      // batch
#define TT   512      // time
#define OBS  64
#define HH   256      // hidden
#define G3   768      // 3*H

// scan v12: 32 batch-groups (8 batches) x 4 unit-slices (64 units) = 128 CTAs
// W held ENTIRELY in registers (48 u64/thread, loaded once).
#define NGB  32
#define NSL  4
#define SNT  512      // scan threads (16 warps)
#define NU   64       // units per CTA
#define NC   192      // gate-cols per CTA (3 gates x 64 units)
#define HPD  264      // h row stride (floats)
#define WSLF (NC * HH)            // floats per W slice (49152)

// dynamic smem carve (bytes) — W cache GONE (registers), xst gone (R15)
#define SM_GS   (8 * 8 * NC * 4)        // 49152 : gsum[frag][b][c]
#define SM_H    (8 * HPD * 4)           // 8448  : hsm[b][k]
#define SCAN_DSMEM (SM_GS + SM_H)       // 57600

typedef unsigned long long u64;

// ---------------- scratch (device globals: allocation-free) ----------------
__device__ float g_xg[(size_t)BB * TT * G3];              // 402 MB gate pre-activations
__device__ float g_y0[(size_t)BB * TT * HH];              // 134 MB layer-0 outputs
__device__ float g_wt[2][(size_t)NSL * WSLF];             // repacked W_hh slices per layer
__device__ float g_mail[(size_t)NGB * NSL * TT * 512];    // h slice mailboxes (134 MB)
__device__ int   g_flag[2][(size_t)NGB * TT * NSL];       // per-layer flags (65536 each)

// ---------------- helpers ----------------
__device__ __forceinline__ float2 unpk(u64 v) {
    float2 f; asm("mov.b64 {%0,%1}, %2;" : "=f"(f.x), "=f"(f.y) : "l"(v)); return f;
}
__device__ __forceinline__ u64 f2fma(u64 a, u64 b, u64 c) {
    u64 d; asm("fma.rn.f32x2 %0, %1, %2, %3;" : "=l"(d) : "l"(a), "l"(b), "l"(c)); return d;
}
__device__ __forceinline__ float sigmf(float x) {
    return 1.0f / (1.0f + __expf(-x));
}
__device__ __forceinline__ float tanh_fast(float x) {
    return 1.0f - __fdividef(2.0f, __expf(2.0f * x) + 1.0f);
}
__device__ __forceinline__ int ld_acq(const int* p) {
    int v; asm volatile("ld.global.acquire.gpu.b32 %0, [%1];" : "=r"(v) : "l"(p)); return v;
}
__device__ __forceinline__ uint32_t cvt_tf32(float x) {
    uint32_t r; asm("cvt.rna.tf32.f32 %0, %1;" : "=r"(r) : "f"(x)); return r;
}
__device__ __forceinline__ void mma_tf32(float* c, const uint32_t* a, const uint32_t* b) {
    asm volatile(
        "mma.sync.aligned.m16n8k8.row.col.f32.tf32.tf32.f32 "
        "{%0,%1,%2,%3}, {%4,%5,%6,%7}, {%8,%9}, {%0,%1,%2,%3};"
        : "+f"(c[0]), "+f"(c[1]), "+f"(c[2]), "+f"(c[3])
        : "r"(a[0]), "r"(a[1]), "r"(a[2]), "r"(a[3]), "r"(b[0]), "r"(b[1]));
}

// =====================================================================
// W_hh repack into 4 unit-slices, quad-major:
//   slice s = u>>6 owns units [64s, 64s+64); local col c = gate*64 + (u&63)
// =====================================================================
__global__ void repack_whh(const float* __restrict__ W, float* __restrict__ out)
{
    const int gRow = blockIdx.x;      // 0..767
    const int k    = threadIdx.x;     // 0..255
    const float v  = W[(size_t)gRow * HH + k];
    const int gate = gRow >> 8;
    const int u    = gRow & 255;
    const int s    = u >> 6;
    const int c    = gate * NU + (u & 63);
    out[(size_t)s * WSLF + (size_t)(k >> 2) * (NC * 4) + c * 4 + (k & 3)] = v;
}

__global__ void reset_flags(int* __restrict__ f)
{
    f[blockIdx.x * 1024 + threadIdx.x] = 0;   // 64 x 1024 = 65536 per layer
}

// =====================================================================
// Projection GEMM (tf32 tensor cores), unchanged from R9:
//   C[M][768] = A[M][K] @ W[768][K]^T + bias[768]
// =====================================================================
#define TBM 128
#define TBN 64
#define TBK 32

__global__ void __launch_bounds__(256) proj_tf32(
    const float* __restrict__ A, const float* __restrict__ Wt,
    const float* __restrict__ bias, float* __restrict__ C, int K)
{
    __shared__ float As[TBK][TBM + 4];
    __shared__ float Bs[TBK][TBN + 4];

    const int tid  = threadIdx.x;
    const int lane = tid & 31;
    const int warp = tid >> 5;
    const int wm   = warp & 3;
    const int wn   = warp >> 2;
    const int gid  = lane >> 2;
    const int tig  = lane & 3;
    const int m0   = blockIdx.y * TBM;
    const int n0   = blockIdx.x * TBN;

    float acc[2][4][4];
    #pragma unroll
    for (int mt = 0; mt < 2; ++mt)
        #pragma unroll
        for (int nt = 0; nt < 4; ++nt)
            #pragma unroll
            for (int r = 0; r < 4; ++r) acc[mt][nt][r] = 0.f;

    for (int k0 = 0; k0 < K; k0 += TBK) {
        #pragma unroll
        for (int i = 0; i < 4; ++i) {
            const int linear = tid + i * 256;
            const int row = linear >> 3;
            const int kq  = (linear & 7) << 2;
            float4 v = *(const float4*)&A[(size_t)(m0 + row) * K + k0 + kq];
            As[kq + 0][row] = v.x; As[kq + 1][row] = v.y;
            As[kq + 2][row] = v.z; As[kq + 3][row] = v.w;
        }
        #pragma unroll
        for (int i = 0; i < 2; ++i) {
            const int linear = tid + i * 256;
            const int row = linear >> 3;
            const int kq  = (linear & 7) << 2;
            float4 v = *(const float4*)&Wt[(size_t)(n0 + row) * K + k0 + kq];
            Bs[kq + 0][row] = v.x; Bs[kq + 1][row] = v.y;
            Bs[kq + 2][row] = v.z; Bs[kq + 3][row] = v.w;
        }
        __syncthreads();

        #pragma unroll
        for (int ks = 0; ks < TBK; ks += 8) {
            uint32_t af[2][4], bf[4][2];
            #pragma unroll
            for (int mt = 0; mt < 2; ++mt) {
                const int rm = wm * 32 + mt * 16 + gid;
                af[mt][0] = cvt_tf32(As[ks + tig][rm]);
                af[mt][1] = cvt_tf32(As[ks + tig][rm + 8]);
                af[mt][2] = cvt_tf32(As[ks + tig + 4][rm]);
                af[mt][3] = cvt_tf32(As[ks + tig + 4][rm + 8]);
            }
            #pragma unroll
            for (int nt = 0; nt < 4; ++nt) {
                const int nb = wn * 32 + nt * 8 + gid;
                bf[nt][0] = cvt_tf32(Bs[ks + tig][nb]);
                bf[nt][1] = cvt_tf32(Bs[ks + tig + 4][nb]);
            }
            #pragma unroll
            for (int mt = 0; mt < 2; ++mt)
                #pragma unroll
                for (int nt = 0; nt < 4; ++nt)
                    mma_tf32(acc[mt][nt], af[mt], bf[nt]);
        }
        __syncthreads();
    }

    #pragma unroll
    for (int mt = 0; mt < 2; ++mt) {
        const int rm = m0 + wm * 32 + mt * 16 + gid;
        #pragma unroll
        for (int nt = 0; nt < 4; ++nt) {
            const int nc = n0 + wn * 32 + nt * 8 + 2 * tig;
            const float b0 = bias[nc], b1 = bias[nc + 1];
            *(float2*)&C[(size_t)rm * G3 + nc] =
                make_float2(acc[mt][nt][0] + b0, acc[mt][nt][1] + b1);
            *(float2*)&C[(size_t)(rm + 8) * G3 + nc] =
                make_float2(acc[mt][nt][2] + b0, acc[mt][nt][3] + b1);
        }
    }
}

// =====================================================================
// Recurrent scan v12 — R15's 4-way split x 8 batches, with the thread's
// ENTIRE W footprint (8 quads x 3 gates = 48 u64) held in registers,
// loaded once before the t-loop. Zero W memory traffic in the hot loop.
// Exchange: L2 mail + per-slice flags (proven R13/R15 protocol).
// =====================================================================
template<bool WRITE_Y>
__global__ void __launch_bounds__(SNT) scan_kernel(
    const float* __restrict__ xg, const float* __restrict__ wsl_base,
    const float* __restrict__ bhh, float* __restrict__ y, float* __restrict__ hout,
    float* __restrict__ mail, int* __restrict__ flag)
{
    extern __shared__ __align__(16) unsigned char sraw[];
    float* gsum = (float*)sraw;                        // [frag 8][b 8][NC]
    float* hsm  = (float*)(sraw + SM_GS);              // [b 8][HPD]

    const int tid = threadIdx.x;
    const int bid = blockIdx.x;
    const int gb  = bid >> 2;             // batch group
    const int so  = bid & 3;              // own unit slice / quarter
    const int bb0 = gb * 8;

    const int j   = tid & 63;             // unit within slice (dot) / unit (combine)
    const int ke  = tid >> 6;             // k-eighth (dot) / batch (combine)
    const int qtr = ke >> 1;              // k-quarter this thread consumes
    const int q0  = ke * 8;               // first quad

    const ulonglong2* __restrict__ wtu =
        (const ulonglong2*)(wsl_base + (size_t)so * WSLF);     // [64][NC]

    // ---- load this thread's entire W footprint into registers ----
    ulonglong2 wr_[8], wz_[8], wn_[8];
    #pragma unroll
    for (int i = 0; i < 8; ++i) {
        const ulonglong2* wq = wtu + (size_t)(q0 + i) * NC;
        wr_[i] = wq[j];
        wz_[i] = wq[NU + j];
        wn_[i] = wq[2 * NU + j];
    }

    // zero h
    for (int i = tid; i < 8 * HPD; i += SNT)
        hsm[i] = 0.f;

    // combine constants (all 512 threads combine: b=ke, unit j)
    const int gj = so * NU + j;
    const float br = bhh[gj];
    const float bz = bhh[HH + gj];
    const float bn = bhh[2 * HH + gj];

    const size_t STRB  = (size_t)TT * G3;
    const size_t STRBY = (size_t)TT * HH;
    // x loader == combine thread: (b=ke, unit gj), 3 gates
    const float* xbase = xg + (size_t)(bb0 + ke) * STRB + so * NU + j;

    float* mail_out = mail + ((size_t)(gb * NSL + so) * TT) * 512;
    const float* mail_src = mail + ((size_t)(gb * NSL + qtr) * TT) * 512;
    int* flag_grp = flag + (size_t)gb * TT * NSL;

    // peer-copy mapping: 128 threads per quarter, local idx lt
    const int lt = (ke & 1) * 64 + j;              // 0..127
    const int cp_b = lt >> 4;                      // batch 0..7
    const int cp_u = (lt & 15) << 2;               // unit 0,4,..,60

    __syncthreads();

    for (int t = 0; t < TT; ++t) {
        // ---- x loads (stay in registers across the whole step) ----
        const float* xp = xbase + (size_t)t * G3;
        const float xr_ = xp[0];
        const float xz_ = xp[256];
        const float xn_ = xp[512];

        // ---- acquire peer quarter h(t-1), copy to smem ----
        if (qtr != so && t > 0) {
            const int* fp = flag_grp + (size_t)(t - 1) * NSL + qtr;
            while (ld_acq(fp) == 0) { }
            float4 v = *(const float4*)&mail_src[(size_t)(t - 1) * 512 + lt * 4];
            *(float4*)&hsm[cp_b * HPD + qtr * NU + cp_u] = v;
            asm volatile("bar.sync %0, 128;" :: "r"(1 + qtr) : "memory");
        }

        // ---- dot: 3 gate-cols x 8 batches x 8 quads, W from REGISTERS ----
        u64 ar[8], az[8], an[8];
        #pragma unroll
        for (int b = 0; b < 8; ++b) { ar[b] = 0; az[b] = 0; an[b] = 0; }

        #pragma unroll
        for (int i = 0; i < 8; ++i) {
            const int q = q0 + i;
            const ulonglong2 wr = wr_[i];
            const ulonglong2 wz = wz_[i];
            const ulonglong2 wn = wn_[i];
            #pragma unroll
            for (int b = 0; b < 8; ++b) {
                ulonglong2 h = *(const ulonglong2*)&hsm[b * HPD + 4 * q];
                ar[b] = f2fma(wr.x, h.x, ar[b]); ar[b] = f2fma(wr.y, h.y, ar[b]);
                az[b] = f2fma(wz.x, h.x, az[b]); az[b] = f2fma(wz.y, h.y, az[b]);
                an[b] = f2fma(wn.x, h.x, an[b]); an[b] = f2fma(wn.y, h.y, an[b]);
            }
        }

        // ---- fold k-pair lanes, publish fragments ----
        #pragma unroll
        for (int b = 0; b < 8; ++b) {
            float2 fr = unpk(ar[b]), fz = unpk(az[b]), fn = unpk(an[b]);
            float* gs = gsum + (ke * 8 + b) * NC;
            gs[j]          = fr.x + fr.y;
            gs[NU + j]     = fz.x + fz.y;
            gs[2 * NU + j] = fn.x + fn.y;
        }
        __syncthreads();

        // ---- combine: thread (b=ke, j) does its single (unit,batch) item ----
        {
            const int b = ke;
            float R = 0.f, Z = 0.f, Nv = 0.f;
            #pragma unroll
            for (int f = 0; f < 8; ++f) {
                const float* gs = gsum + (f * 8 + b) * NC;
                R  += gs[j];
                Z  += gs[NU + j];
                Nv += gs[2 * NU + j];
            }
            const float rr = sigmf(R + xr_ + br);
            const float zz = sigmf(Z + xz_ + bz);
            const float nn = tanh_fast(xn_ + rr * (Nv + bn));
            const float h = (1.0f - zz) * nn + zz * hsm[b * HPD + gj];
            hsm[b * HPD + gj] = h;
            mail_out[(size_t)t * 512 + b * NU + j] = h;
            if (WRITE_Y)
                y[(size_t)(bb0 + b) * STRBY + (size_t)t * HH + gj] = h;
        }
        __syncthreads();

        // ---- release own slice h(t) ----
        if (tid == 0) {
            __threadfence();
            atomicExch(flag_grp + (size_t)t * NSL + so, 1);
        }
    }

    if (!WRITE_Y) {
        hout[(size_t)(bb0 + ke) * HH + gj] = hsm[ke * HPD + gj];
    }
}

// =====================================================================
// launch
// =====================================================================
extern "C" void kernel_launch(void* const* d_in, const int* in_sizes, int n_in,
                              void* d_out, int out_size)
{
    const float* obs   = (const float*)d_in[0];
    const float* w_ih0 = (const float*)d_in[1];
    const float* w_hh0 = (const float*)d_in[2];
    const float* b_ih0 = (const float*)d_in[3];
    const float* b_hh0 = (const float*)d_in[4];
    const float* w_ih1 = (const float*)d_in[5];
    const float* w_hh1 = (const float*)d_in[6];
    const float* b_ih1 = (const float*)d_in[7];
    const float* b_hh1 = (const float*)d_in[8];
    float* out = (float*)d_out;

    void* xg_p = nullptr;  cudaGetSymbolAddress(&xg_p, g_xg);
    void* y0_p = nullptr;  cudaGetSymbolAddress(&y0_p, g_y0);
    void* wt_p = nullptr;  cudaGetSymbolAddress(&wt_p, g_wt);
    void* ml_p = nullptr;  cudaGetSymbolAddress(&ml_p, g_mail);
    void* fl_p = nullptr;  cudaGetSymbolAddress(&fl_p, g_flag);
    float* xg   = (float*)xg_p;
    float* y0   = (float*)y0_p;
    float* mail = (float*)ml_p;
    float* wsl0 = (float*)wt_p;
    float* wsl1 = wsl0 + (size_t)NSL * WSLF;
    int*   flag0 = (int*)fl_p;
    int*   flag1 = flag0 + (size_t)NGB * TT * NSL;

    cudaFuncSetAttribute(scan_kernel<true>,  cudaFuncAttributeMaxDynamicSharedMemorySize, SCAN_DSMEM);
    cudaFuncSetAttribute(scan_kernel<false>, cudaFuncAttributeMaxDynamicSharedMemorySize, SCAN_DSMEM);

    const int M = BB * TT;                 // 131072
    dim3 pgrid(G3 / TBN, M / TBM);         // (12, 1024)

    // launches 1-4: resets + repacks
    reset_flags<<<64, 1024>>>(flag0);
    reset_flags<<<64, 1024>>>(flag1);
    repack_whh<<<G3, HH>>>(w_hh0, wsl0);
    repack_whh<<<G3, HH>>>(w_hh1, wsl1);

    // layer 0
    proj_tf32<<<pgrid, 256>>>(obs, w_ih0, b_ih0, xg, OBS);
    scan_kernel<true><<<NGB * NSL, SNT, SCAN_DSMEM>>>(xg, wsl0, b_hh0, y0, nullptr, mail, flag0);
    // layer 1
    proj_tf32<<<pgrid, 256>>>(y0, w_ih1, b_ih1, xg, HH);
    scan_kernel<false><<<NGB * NSL, SNT, SCAN_DSMEM>>>(xg, wsl1, b_hh1, nullptr, out, mail, flag1);
}

// round 17
// speedup vs baseline: 1.4118x; 1.4118x over previous
#include <cuda_runtime.h>
#include <cstdint>
#include <cstddef>

// Problem dims
#define BB   256      // batch
#define TT   512      // time
#define OBS  64
#define HH   256      // hidden
#define G3   768      // 3*H

// scan v13: 32 batch-groups (8 batches) x 4 unit-slices (64 units) = 128 CTAs
// W split: first 4 quads of each k-eighth in REGISTERS (24 regs), last 4 in smem.
#define NGB  32
#define NSL  4
#define SNT  512      // scan threads (16 warps)
#define NU   64       // units per CTA
#define NC   192      // gate-cols per CTA (3 gates x 64 units)
#define HPD  264      // h row stride (floats)
#define WSLF (NC * HH)            // floats per W slice (49152)

// dynamic smem carve (bytes)
#define SM_W    (32 * NC * 16)          // 98304 : quads with (q&7)>=4
#define SM_GS   (8 * 8 * NC * 4)        // 49152 : gsum[frag][b][c]
#define SM_H    (8 * HPD * 4)           // 8448  : hsm[b][k]
#define SCAN_DSMEM (SM_W + SM_GS + SM_H)   // 155904

typedef unsigned long long u64;

// ---------------- scratch (device globals: allocation-free) ----------------
__device__ float g_xg[(size_t)BB * TT * G3];              // 402 MB gate pre-activations
__device__ float g_y0[(size_t)BB * TT * HH];              // 134 MB layer-0 outputs
__device__ float g_wt[2][(size_t)NSL * WSLF];             // repacked W_hh slices per layer
__device__ float g_mail[(size_t)NGB * NSL * TT * 512];    // h slice mailboxes (134 MB)
__device__ int   g_flag[2][(size_t)NGB * TT * NSL];       // per-layer flags (65536 each)

// ---------------- helpers ----------------
__device__ __forceinline__ float2 unpk(u64 v) {
    float2 f; asm("mov.b64 {%0,%1}, %2;" : "=f"(f.x), "=f"(f.y) : "l"(v)); return f;
}
__device__ __forceinline__ u64 f2fma(u64 a, u64 b, u64 c) {
    u64 d; asm("fma.rn.f32x2 %0, %1, %2, %3;" : "=l"(d) : "l"(a), "l"(b), "l"(c)); return d;
}
__device__ __forceinline__ float sigmf(float x) {
    return 1.0f / (1.0f + __expf(-x));
}
__device__ __forceinline__ float tanh_fast(float x) {
    return 1.0f - __fdividef(2.0f, __expf(2.0f * x) + 1.0f);
}
__device__ __forceinline__ int ld_acq(const int* p) {
    int v; asm volatile("ld.global.acquire.gpu.b32 %0, [%1];" : "=r"(v) : "l"(p)); return v;
}
__device__ __forceinline__ uint32_t cvt_tf32(float x) {
    uint32_t r; asm("cvt.rna.tf32.f32 %0, %1;" : "=r"(r) : "f"(x)); return r;
}
__device__ __forceinline__ void mma_tf32(float* c, const uint32_t* a, const uint32_t* b) {
    asm volatile(
        "mma.sync.aligned.m16n8k8.row.col.f32.tf32.tf32.f32 "
        "{%0,%1,%2,%3}, {%4,%5,%6,%7}, {%8,%9}, {%0,%1,%2,%3};"
        : "+f"(c[0]), "+f"(c[1]), "+f"(c[2]), "+f"(c[3])
        : "r"(a[0]), "r"(a[1]), "r"(a[2]), "r"(a[3]), "r"(b[0]), "r"(b[1]));
}

// =====================================================================
// W_hh repack into 4 unit-slices, quad-major:
//   slice s = u>>6 owns units [64s, 64s+64); local col c = gate*64 + (u&63)
// =====================================================================
__global__ void repack_whh(const float* __restrict__ W, float* __restrict__ out)
{
    const int gRow = blockIdx.x;      // 0..767
    const int k    = threadIdx.x;     // 0..255
    const float v  = W[(size_t)gRow * HH + k];
    const int gate = gRow >> 8;
    const int u    = gRow & 255;
    const int s    = u >> 6;
    const int c    = gate * NU + (u & 63);
    out[(size_t)s * WSLF + (size_t)(k >> 2) * (NC * 4) + c * 4 + (k & 3)] = v;
}

__global__ void reset_flags(int* __restrict__ f)
{
    f[blockIdx.x * 1024 + threadIdx.x] = 0;   // 64 x 1024 = 65536 per layer
}

// =====================================================================
// Projection GEMM (tf32 tensor cores), unchanged from R9:
//   C[M][768] = A[M][K] @ W[768][K]^T + bias[768]
// =====================================================================
#define TBM 128
#define TBN 64
#define TBK 32

__global__ void __launch_bounds__(256) proj_tf32(
    const float* __restrict__ A, const float* __restrict__ Wt,
    const float* __restrict__ bias, float* __restrict__ C, int K)
{
    __shared__ float As[TBK][TBM + 4];
    __shared__ float Bs[TBK][TBN + 4];

    const int tid  = threadIdx.x;
    const int lane = tid & 31;
    const int warp = tid >> 5;
    const int wm   = warp & 3;
    const int wn   = warp >> 2;
    const int gid  = lane >> 2;
    const int tig  = lane & 3;
    const int m0   = blockIdx.y * TBM;
    const int n0   = blockIdx.x * TBN;

    float acc[2][4][4];
    #pragma unroll
    for (int mt = 0; mt < 2; ++mt)
        #pragma unroll
        for (int nt = 0; nt < 4; ++nt)
            #pragma unroll
            for (int r = 0; r < 4; ++r) acc[mt][nt][r] = 0.f;

    for (int k0 = 0; k0 < K; k0 += TBK) {
        #pragma unroll
        for (int i = 0; i < 4; ++i) {
            const int linear = tid + i * 256;
            const int row = linear >> 3;
            const int kq  = (linear & 7) << 2;
            float4 v = *(const float4*)&A[(size_t)(m0 + row) * K + k0 + kq];
            As[kq + 0][row] = v.x; As[kq + 1][row] = v.y;
            As[kq + 2][row] = v.z; As[kq + 3][row] = v.w;
        }
        #pragma unroll
        for (int i = 0; i < 2; ++i) {
            const int linear = tid + i * 256;
            const int row = linear >> 3;
            const int kq  = (linear & 7) << 2;
            float4 v = *(const float4*)&Wt[(size_t)(n0 + row) * K + k0 + kq];
            Bs[kq + 0][row] = v.x; Bs[kq + 1][row] = v.y;
            Bs[kq + 2][row] = v.z; Bs[kq + 3][row] = v.w;
        }
        __syncthreads();

        #pragma unroll
        for (int ks = 0; ks < TBK; ks += 8) {
            uint32_t af[2][4], bf[4][2];
            #pragma unroll
            for (int mt = 0; mt < 2; ++mt) {
                const int rm = wm * 32 + mt * 16 + gid;
                af[mt][0] = cvt_tf32(As[ks + tig][rm]);
                af[mt][1] = cvt_tf32(As[ks + tig][rm + 8]);
                af[mt][2] = cvt_tf32(As[ks + tig + 4][rm]);
                af[mt][3] = cvt_tf32(As[ks + tig + 4][rm + 8]);
            }
            #pragma unroll
            for (int nt = 0; nt < 4; ++nt) {
                const int nb = wn * 32 + nt * 8 + gid;
                bf[nt][0] = cvt_tf32(Bs[ks + tig][nb]);
                bf[nt][1] = cvt_tf32(Bs[ks + tig + 4][nb]);
            }
            #pragma unroll
            for (int mt = 0; mt < 2; ++mt)
                #pragma unroll
                for (int nt = 0; nt < 4; ++nt)
                    mma_tf32(acc[mt][nt], af[mt], bf[nt]);
        }
        __syncthreads();
    }

    #pragma unroll
    for (int mt = 0; mt < 2; ++mt) {
        const int rm = m0 + wm * 32 + mt * 16 + gid;
        #pragma unroll
        for (int nt = 0; nt < 4; ++nt) {
            const int nc = n0 + wn * 32 + nt * 8 + 2 * tig;
            const float b0 = bias[nc], b1 = bias[nc + 1];
            *(float2*)&C[(size_t)rm * G3 + nc] =
                make_float2(acc[mt][nt][0] + b0, acc[mt][nt][1] + b1);
            *(float2*)&C[(size_t)(rm + 8) * G3 + nc] =
                make_float2(acc[mt][nt][2] + b0, acc[mt][nt][3] + b1);
        }
    }
}

// =====================================================================
// Recurrent scan v13 — R15's 4-way split x 8 batches; W hybrid:
// quads (q&7)<4 of each k-eighth in registers (12 ulonglong2 = 24 regs),
// quads (q&7)>=4 in a 32-quad smem cache. Exchange: L2 mail + per-slice
// flags (proven R13/R15 protocol). x stays in registers (R15).
// =====================================================================
template<bool WRITE_Y>
__global__ void __launch_bounds__(SNT) scan_kernel(
    const float* __restrict__ xg, const float* __restrict__ wsl_base,
    const float* __restrict__ bhh, float* __restrict__ y, float* __restrict__ hout,
    float* __restrict__ mail, int* __restrict__ flag)
{
    extern __shared__ __align__(16) unsigned char sraw[];
    ulonglong2* Wc = (ulonglong2*)sraw;                // [32 rows][NC]: quad (r/4)*8+4+(r%4)
    float* gsum = (float*)(sraw + SM_W);               // [frag 8][b 8][NC]
    float* hsm  = (float*)(sraw + SM_W + SM_GS);       // [b 8][HPD]

    const int tid = threadIdx.x;
    const int bid = blockIdx.x;
    const int gb  = bid >> 2;             // batch group
    const int so  = bid & 3;              // own unit slice / quarter
    const int bb0 = gb * 8;

    const int j   = tid & 63;             // unit within slice (dot) / unit (combine)
    const int ke  = tid >> 6;             // k-eighth (dot) / batch (combine)
    const int qtr = ke >> 1;              // k-quarter this thread consumes
    const int q0  = ke * 8;               // first quad

    const ulonglong2* __restrict__ wtu =
        (const ulonglong2*)(wsl_base + (size_t)so * WSLF);     // [64][NC]

    // ---- register W: first 4 quads of this thread's eighth ----
    ulonglong2 wr_[4], wz_[4], wn_[4];
    #pragma unroll
    for (int i = 0; i < 4; ++i) {
        const ulonglong2* wq = wtu + (size_t)(q0 + i) * NC;
        wr_[i] = wq[j];
        wz_[i] = wq[NU + j];
        wn_[i] = wq[2 * NU + j];
    }

    // ---- smem W cache: quads with (q&7)>=4; row r = (q>>3)*4 + (q&7)-4 ----
    for (int i = tid; i < 32 * NC; i += SNT) {
        const int row = i / NC, c = i % NC;
        const int q = (row >> 2) * 8 + 4 + (row & 3);
        Wc[i] = wtu[(size_t)q * NC + c];
    }
    // zero h
    for (int i = tid; i < 8 * HPD; i += SNT)
        hsm[i] = 0.f;

    // combine constants (all 512 threads combine: b=ke, unit j)
    const int gj = so * NU + j;
    const float br = bhh[gj];
    const float bz = bhh[HH + gj];
    const float bn = bhh[2 * HH + gj];

    const size_t STRB  = (size_t)TT * G3;
    const size_t STRBY = (size_t)TT * HH;
    // x loader == combine thread: (b=ke, unit gj), 3 gates
    const float* xbase = xg + (size_t)(bb0 + ke) * STRB + so * NU + j;

    float* mail_out = mail + ((size_t)(gb * NSL + so) * TT) * 512;
    const float* mail_src = mail + ((size_t)(gb * NSL + qtr) * TT) * 512;
    int* flag_grp = flag + (size_t)gb * TT * NSL;

    // peer-copy mapping: 128 threads per quarter, local idx lt
    const int lt = (ke & 1) * 64 + j;              // 0..127
    const int cp_b = lt >> 4;                      // batch 0..7
    const int cp_u = (lt & 15) << 2;               // unit 0,4,..,60

    __syncthreads();

    for (int t = 0; t < TT; ++t) {
        // ---- x loads (stay in registers across the whole step) ----
        const float* xp = xbase + (size_t)t * G3;
        const float xr_ = xp[0];
        const float xz_ = xp[256];
        const float xn_ = xp[512];

        // ---- acquire peer quarter h(t-1), copy to smem ----
        if (qtr != so && t > 0) {
            const int* fp = flag_grp + (size_t)(t - 1) * NSL + qtr;
            while (ld_acq(fp) == 0) { }
            float4 v = *(const float4*)&mail_src[(size_t)(t - 1) * 512 + lt * 4];
            *(float4*)&hsm[cp_b * HPD + qtr * NU + cp_u] = v;
            asm volatile("bar.sync %0, 128;" :: "r"(1 + qtr) : "memory");
        }

        // ---- dot: 3 gate-cols x 8 batches x 8 quads ----
        u64 ar[8], az[8], an[8];
        #pragma unroll
        for (int b = 0; b < 8; ++b) { ar[b] = 0; az[b] = 0; an[b] = 0; }

        // quads 0..3: W from REGISTERS
        #pragma unroll
        for (int i = 0; i < 4; ++i) {
            const int q = q0 + i;
            const ulonglong2 wr = wr_[i];
            const ulonglong2 wz = wz_[i];
            const ulonglong2 wn = wn_[i];
            #pragma unroll
            for (int b = 0; b < 8; ++b) {
                ulonglong2 h = *(const ulonglong2*)&hsm[b * HPD + 4 * q];
                ar[b] = f2fma(wr.x, h.x, ar[b]); ar[b] = f2fma(wr.y, h.y, ar[b]);
                az[b] = f2fma(wz.x, h.x, az[b]); az[b] = f2fma(wz.y, h.y, az[b]);
                an[b] = f2fma(wn.x, h.x, an[b]); an[b] = f2fma(wn.y, h.y, an[b]);
            }
        }
        // quads 4..7: W from smem cache (row = ke*4 + (i-4))
        #pragma unroll
        for (int i = 4; i < 8; ++i) {
            const int q = q0 + i;
            const int row = ke * 4 + (i - 4);
            ulonglong2 wr = Wc[row * NC + j];
            ulonglong2 wz = Wc[row * NC + NU + j];
            ulonglong2 wn = Wc[row * NC + 2 * NU + j];
            #pragma unroll
            for (int b = 0; b < 8; ++b) {
                ulonglong2 h = *(const ulonglong2*)&hsm[b * HPD + 4 * q];
                ar[b] = f2fma(wr.x, h.x, ar[b]); ar[b] = f2fma(wr.y, h.y, ar[b]);
                az[b] = f2fma(wz.x, h.x, az[b]); az[b] = f2fma(wz.y, h.y, az[b]);
                an[b] = f2fma(wn.x, h.x, an[b]); an[b] = f2fma(wn.y, h.y, an[b]);
            }
        }

        // ---- fold k-pair lanes, publish fragments ----
        #pragma unroll
        for (int b = 0; b < 8; ++b) {
            float2 fr = unpk(ar[b]), fz = unpk(az[b]), fn = unpk(an[b]);
            float* gs = gsum + (ke * 8 + b) * NC;
            gs[j]          = fr.x + fr.y;
            gs[NU + j]     = fz.x + fz.y;
            gs[2 * NU + j] = fn.x + fn.y;
        }
        __syncthreads();

        // ---- combine: thread (b=ke, j) does its single (unit,batch) item ----
        {
            const int b = ke;
            float R = 0.f, Z = 0.f, Nv = 0.f;
            #pragma unroll
            for (int f = 0; f < 8; ++f) {
                const float* gs = gsum + (f * 8 + b) * NC;
                R  += gs[j];
                Z  += gs[NU + j];
                Nv += gs[2 * NU + j];
            }
            const float rr = sigmf(R + xr_ + br);
            const float zz = sigmf(Z + xz_ + bz);
            const float nn = tanh_fast(xn_ + rr * (Nv + bn));
            const float h = (1.0f - zz) * nn + zz * hsm[b * HPD + gj];
            hsm[b * HPD + gj] = h;
            mail_out[(size_t)t * 512 + b * NU + j] = h;
            if (WRITE_Y)
                y[(size_t)(bb0 + b) * STRBY + (size_t)t * HH + gj] = h;
        }
        __syncthreads();

        // ---- release own slice h(t) ----
        if (tid == 0) {
            __threadfence();
            atomicExch(flag_grp + (size_t)t * NSL + so, 1);
        }
    }

    if (!WRITE_Y) {
        hout[(size_t)(bb0 + ke) * HH + gj] = hsm[ke * HPD + gj];
    }
}

// =====================================================================
// launch
// =====================================================================
extern "C" void kernel_launch(void* const* d_in, const int* in_sizes, int n_in,
                              void* d_out, int out_size)
{
    const float* obs   = (const float*)d_in[0];
    const float* w_ih0 = (const float*)d_in[1];
    const float* w_hh0 = (const float*)d_in[2];
    const float* b_ih0 = (const float*)d_in[3];
    const float* b_hh0 = (const float*)d_in[4];
    const float* w_ih1 = (const float*)d_in[5];
    const float* w_hh1 = (const float*)d_in[6];
    const float* b_ih1 = (const float*)d_in[7];
    const float* b_hh1 = (const float*)d_in[8];
    float* out = (float*)d_out;

    void* xg_p = nullptr;  cudaGetSymbolAddress(&xg_p, g_xg);
    void* y0_p = nullptr;  cudaGetSymbolAddress(&y0_p, g_y0);
    void* wt_p = nullptr;  cudaGetSymbolAddress(&wt_p, g_wt);
    void* ml_p = nullptr;  cudaGetSymbolAddress(&ml_p, g_mail);
    void* fl_p = nullptr;  cudaGetSymbolAddress(&fl_p, g_flag);
    float* xg   = (float*)xg_p;
    float* y0   = (float*)y0_p;
    float* mail = (float*)ml_p;
    float* wsl0 = (float*)wt_p;
    float* wsl1 = wsl0 + (size_t)NSL * WSLF;
    int*   flag0 = (int*)fl_p;
    int*   flag1 = flag0 + (size_t)NGB * TT * NSL;

    cudaFuncSetAttribute(scan_kernel<true>,  cudaFuncAttributeMaxDynamicSharedMemorySize, SCAN_DSMEM);
    cudaFuncSetAttribute(scan_kernel<false>, cudaFuncAttributeMaxDynamicSharedMemorySize, SCAN_DSMEM);

    const int M = BB * TT;                 // 131072
    dim3 pgrid(G3 / TBN, M / TBM);         // (12, 1024)

    // launches 1-4: resets + repacks
    reset_flags<<<64, 1024>>>(flag0);
    reset_flags<<<64, 1024>>>(flag1);
    repack_whh<<<G3, HH>>>(w_hh0, wsl0);
    repack_whh<<<G3, HH>>>(w_hh1, wsl1);

    // layer 0
    proj_tf32<<<pgrid, 256>>>(obs, w_ih0, b_ih0, xg, OBS);
    scan_kernel<true><<<NGB * NSL, SNT, SCAN_DSMEM>>>(xg, wsl0, b_hh0, y0, nullptr, mail, flag0);
    // layer 1
    proj_tf32<<<pgrid, 256>>>(y0, w_ih1, b_ih1, xg, HH);
    scan_kernel<false><<<NGB * NSL, SNT, SCAN_DSMEM>>>(xg, wsl1, b_hh1, nullptr, out, mail, flag1);
}